// round 5
// baseline (speedup 1.0000x reference)
#include <cuda_runtime.h>
#include <cuda_bf16.h>

// Problem constants
#define BATCH 16
#define SEQ   4096
#define HDIM  1024
#define HN    16      // heads
#define HD    64      // head dim

// ---------------------------------------------------------------------------
// Scratch (device globals: no allocation allowed)
// ---------------------------------------------------------------------------
__device__ float g_q[BATCH * HDIM];          // q = query @ Wq^T + bq
__device__ float g_w[BATCH * HN * HDIM];     // w[b,h,:] = (1/32) Wk_h^T q_h
__device__ float g_c[BATCH * HN];            // (1/32) q_h . bk_h
__device__ float g_u[BATCH * HN * HDIM];     // u[b,h,:] = sum_s att * value_row
__device__ float g_A[BATCH * HN];            // A[b,h]   = sum_s att
__device__ float g_o1[BATCH * HDIM];         // out before final projection

// ---------------------------------------------------------------------------
// f32x2 helpers (packed FFMA2)
// ---------------------------------------------------------------------------
__device__ __forceinline__ void fma2(unsigned long long &d,
                                     unsigned long long a,
                                     unsigned long long b) {
    asm("fma.rn.f32x2 %0, %1, %2, %0;" : "+l"(d) : "l"(a), "l"(b));
}
__device__ __forceinline__ float2 unpack2(unsigned long long v) {
    float2 f;
    asm("mov.b64 {%0, %1}, %2;" : "=f"(f.x), "=f"(f.y) : "l"(v));
    return f;
}
__device__ __forceinline__ unsigned long long pack2(float a, float b) {
    unsigned long long r;
    asm("mov.b64 %0, {%1, %2};" : "=l"(r) : "f"(a), "f"(b));
    return r;
}
__device__ __forceinline__ unsigned long long pack_dup(float a) {
    unsigned long long r;
    asm("mov.b64 %0, {%1, %1};" : "=l"(r) : "f"(a));
    return r;
}
__device__ __forceinline__ unsigned smem_u32(const void* p) {
    unsigned a;
    asm("{ .reg .u64 t; cvta.to.shared.u64 t, %1; cvt.u32.u64 %0, t; }"
        : "=r"(a) : "l"(p));
    return a;
}
__device__ __forceinline__ void cp_async16(unsigned dst, const void* src) {
    asm volatile("cp.async.cg.shared.global [%0], [%1], 16;"
                 :: "r"(dst), "l"(src) : "memory");
}
__device__ __forceinline__ void cp_commit() {
    asm volatile("cp.async.commit_group;" ::: "memory");
}
__device__ __forceinline__ void cp_wait1() {
    asm volatile("cp.async.wait_group 1;" ::: "memory");
}
__device__ __forceinline__ void bar_score() {   // named barrier: score warps only
    asm volatile("bar.sync 1, 256;" ::: "memory");
}

// ---------------------------------------------------------------------------
// K1: q[b,i] = query[b,:] . Wq[i,:] + bq[i]   (warp per output)
// ---------------------------------------------------------------------------
__global__ void k1_q(const float* __restrict__ query,
                     const float* __restrict__ Wq,
                     const float* __restrict__ bq) {
    int gw   = (blockIdx.x * blockDim.x + threadIdx.x) >> 5;
    int lane = threadIdx.x & 31;
    if (gw >= BATCH * HDIM) return;
    int b = gw >> 10, i = gw & 1023;
    const float4* qr = (const float4*)(query + b * HDIM);
    const float4* wr = (const float4*)(Wq + (size_t)i * HDIM);
    float acc = 0.f;
#pragma unroll
    for (int t = 0; t < 8; t++) {
        float4 a = qr[t * 32 + lane];
        float4 w = wr[t * 32 + lane];
        acc += a.x * w.x + a.y * w.y + a.z * w.z + a.w * w.w;
    }
#pragma unroll
    for (int o = 16; o > 0; o >>= 1) acc += __shfl_xor_sync(~0u, acc, o);
    if (lane == 0) g_q[gw] = acc + bq[i];
}

// ---------------------------------------------------------------------------
// K2: w[b,h,j] = (1/32) sum_d q[b,h*64+d] * Wk[h*64+d, j];  also zeros g_u/g_A
// ---------------------------------------------------------------------------
__global__ void k2_w(const float* __restrict__ Wk,
                     const float* __restrict__ bk) {
    int h = blockIdx.x >> 4;
    int b = blockIdx.x & 15;
    int tid = threadIdx.x;

    int gtid = blockIdx.x * 256 + tid;
    ((float4*)g_u)[gtid] = make_float4(0.f, 0.f, 0.f, 0.f);
    if (gtid < BATCH * HN) g_A[gtid] = 0.f;

    __shared__ float qh[HD];
    if (tid < HD) qh[tid] = g_q[b * HDIM + h * HD + tid];
    __syncthreads();

    float4 acc = make_float4(0.f, 0.f, 0.f, 0.f);
    const float4* wk = (const float4*)(Wk + (size_t)(h * HD) * HDIM) + tid;
#pragma unroll 8
    for (int d = 0; d < HD; d++) {
        float4 v = wk[d * 256];
        float  s = qh[d];
        acc.x += s * v.x; acc.y += s * v.y; acc.z += s * v.z; acc.w += s * v.w;
    }
    const float scale = 0.03125f;  // 1/sqrt(1024)
    acc.x *= scale; acc.y *= scale; acc.z *= scale; acc.w *= scale;
    ((float4*)(g_w + (b * HN + h) * HDIM))[tid] = acc;

    if (tid == 0) {
        float cc = 0.f;
        for (int d = 0; d < HD; d++) cc += qh[d] * bk[h * HD + d];
        g_c[b * HN + h] = cc * scale;
    }
}

// ---------------------------------------------------------------------------
// K3 fused: warp-specialized scores+softmax+accumulate.
//  grid (8 chunks of 512 rows, 16 b) = 128 CTAs (single wave), 512 threads,
//  1 CTA/SM. Warps 0-7 = SCORE role (w register-resident, key via cp.async
//  double buffer, softmax; writes packed att to smem ring). Warps 8-15 =
//  ACCUM role (u register-resident, value via batched LDG; consumes att of
//  the previous stage). One __syncthreads per 8-row stage; score-internal
//  ordering uses named barrier 1 (256 threads) so accum never waits on it.
// ---------------------------------------------------------------------------
#define FK3_STAGES 64            // 512 rows / 8
__global__ __launch_bounds__(512, 1)
void k3_fused(const float* __restrict__ key,
              const float* __restrict__ value) {
    extern __shared__ float smem_raw[];
    float* kbuf = smem_raw;                                    // 2 x 8 x 1024 floats
    float* part = kbuf + 16384;                                // 8 warps x 8 rows x 16 heads
    unsigned long long* att_pk = (unsigned long long*)(part + 1024);  // 2 x 128 packed {a,a}
    float* c_s = (float*)(att_pk + 256);                       // 16 floats

    const int b     = blockIdx.y;
    const int chunk = blockIdx.x;
    const int tid   = threadIdx.x;
    const int wid   = tid >> 5;
    const int lane  = tid & 31;
    const int row0  = chunk * 512;

    if (tid < HN) c_s[tid] = g_c[b * HN + tid];

    if (wid < 8) {
        // ================= SCORE role (threads 0..255) =================
        const int h     = lane & 15;
        const int jhalf = lane >> 4;
        const int slice_off = wid * 128 + jhalf * 64;

        unsigned long long wreg[32];
        {
            const float4* wsrc = (const float4*)(g_w + (size_t)(b * HN + h) * HDIM + slice_off);
#pragma unroll
            for (int t = 0; t < 16; t++) {
                float4 f = wsrc[t];
                wreg[2 * t + 0] = pack2(f.x, f.y);
                wreg[2 * t + 1] = pack2(f.z, f.w);
            }
        }

        const float* keyb = key + (size_t)b * SEQ * HDIM;
        const unsigned kbuf_addr = smem_u32(kbuf);

        // prologue: prefetch stages 0 and 1
#pragma unroll
        for (int s = 0; s < 2; s++) {
            const float* src = keyb + (size_t)(row0 + s * 8) * HDIM;
#pragma unroll
            for (int c = 0; c < 8; c++)
                cp_async16(kbuf_addr + (s * 8192 + c * 1024 + tid * 4) * 4,
                           src + c * 1024 + tid * 4);
            cp_commit();
        }

        for (int s = 0; s <= FK3_STAGES; s++) {
            if (s < FK3_STAGES) {
                const int buf = s & 1;
                cp_wait1();
                bar_score();

                // scores for 8 rows from smem broadcast
                const float4* kb = (const float4*)(kbuf + buf * 8192) + (slice_off >> 2);
                float* pdst = part + wid * 128 + h;
#pragma unroll
                for (int r = 0; r < 8; r++) {
                    unsigned long long acc = 0ULL;
                    const float4* krow = kb + r * 256;
#pragma unroll
                    for (int t = 0; t < 16; t++) {
                        float4 kv = krow[t];
                        fma2(acc, pack2(kv.x, kv.y), wreg[2 * t + 0]);
                        fma2(acc, pack2(kv.z, kv.w), wreg[2 * t + 1]);
                    }
                    float2 fa = unpack2(acc);
                    float f = fa.x + fa.y;
                    f += __shfl_xor_sync(~0u, f, 16);
                    if (lane < 16) pdst[r * 16] = f;
                }
                bar_score();

                // refill kbuf[buf] with stage s+2
                if (s + 2 < FK3_STAGES) {
                    const float* src = keyb + (size_t)(row0 + (s + 2) * 8) * HDIM;
#pragma unroll
                    for (int c = 0; c < 8; c++)
                        cp_async16(kbuf_addr + (buf * 8192 + c * 1024 + tid * 4) * 4,
                                   src + c * 1024 + tid * 4);
                }
                cp_commit();

                // softmax: thread t<128 = (row t>>4, head t&15)
                if (tid < 128) {
                    const int r = tid >> 4, hh = tid & 15;
                    const float* psrc = part + r * 16 + hh;
                    float sc = c_s[hh];
#pragma unroll
                    for (int w8 = 0; w8 < 8; w8++) sc += psrc[w8 * 128];
                    float m = sc;
#pragma unroll
                    for (int o = 8; o > 0; o >>= 1) m = fmaxf(m, __shfl_xor_sync(~0u, m, o));
                    float e = __expf(sc - m);
                    float sum = e;
#pragma unroll
                    for (int o = 8; o > 0; o >>= 1) sum += __shfl_xor_sync(~0u, sum, o);
                    att_pk[buf * 128 + tid] = pack_dup(__fdividef(e, sum));
                }
            }
            __syncthreads();
        }
    } else {
        // ================= ACCUM role (threads 256..511) =================
        const int aw = wid - 8;
        const int j0 = aw * 128 + lane * 4;
        const float* valb = value + (size_t)b * SEQ * HDIM;

        unsigned long long u2[32];
#pragma unroll
        for (int i = 0; i < 32; i++) u2[i] = 0ULL;
        float a_loc = 0.f;

        for (int s = 0; s <= FK3_STAGES; s++) {
            if (s >= 1) {
                const int t = s - 1;
                const int rbase = row0 + t * 8;
                const unsigned long long* ap = att_pk + (t & 1) * 128;

                ulonglong2 vv[8];
#pragma unroll
                for (int r = 0; r < 8; r++)
                    vv[r] = *(const ulonglong2*)(valb + (size_t)(rbase + r) * HDIM + j0);
#pragma unroll
                for (int r = 0; r < 8; r++) {
#pragma unroll
                    for (int hh = 0; hh < 16; hh++) {
                        unsigned long long a2 = ap[r * 16 + hh];   // broadcast LDS.64
                        fma2(u2[2 * hh + 0], a2, vv[r].x);
                        fma2(u2[2 * hh + 1], a2, vv[r].y);
                    }
                }
                if (aw == 0 && lane < 16) {
#pragma unroll
                    for (int r = 0; r < 8; r++)
                        a_loc += unpack2(ap[r * 16 + lane]).x;
                }
            }
            __syncthreads();
        }

        // flush u partials (8 CTAs per b contend per address — fine)
        float* ubase = g_u + (b * HN) * HDIM + j0;
#pragma unroll
        for (int hh = 0; hh < 16; hh++) {
            float2 lo = unpack2(u2[2 * hh + 0]);
            float2 hi = unpack2(u2[2 * hh + 1]);
            atomicAdd(ubase + (hh << 10) + 0, lo.x);
            atomicAdd(ubase + (hh << 10) + 1, lo.y);
            atomicAdd(ubase + (hh << 10) + 2, hi.x);
            atomicAdd(ubase + (hh << 10) + 3, hi.y);
        }
        if (aw == 0 && lane < 16) atomicAdd(&g_A[b * HN + lane], a_loc);
    }
}

// ---------------------------------------------------------------------------
// K4: o1[b,j] = Wv[j,:] . u[b, j/64, :] + bv[j] * A[b, j/64]   warp per (j,b)
// ---------------------------------------------------------------------------
__global__ void k4_out(const float* __restrict__ Wv,
                       const float* __restrict__ bv) {
    int gw   = (blockIdx.x * blockDim.x + threadIdx.x) >> 5;
    int lane = threadIdx.x & 31;
    if (gw >= HDIM * BATCH) return;
    int b = gw & 15, j = gw >> 4, h = j >> 6;
    const float4* wr = (const float4*)(Wv + (size_t)j * HDIM);
    const float4* ur = (const float4*)(g_u + (b * HN + h) * HDIM);
    float acc = 0.f;
#pragma unroll
    for (int t = 0; t < 8; t++) {
        float4 w = wr[t * 32 + lane];
        float4 u = ur[t * 32 + lane];
        acc += w.x * u.x + w.y * u.y + w.z * u.z + w.w * u.w;
    }
#pragma unroll
    for (int o = 16; o > 0; o >>= 1) acc += __shfl_xor_sync(~0u, acc, o);
    if (lane == 0) g_o1[b * HDIM + j] = acc + bv[j] * g_A[b * HN + h];
}

// ---------------------------------------------------------------------------
// K5: res[b,i] = Wf[i,:] . o1[b,:] + bf[i]   warp per (i,b)
// ---------------------------------------------------------------------------
__global__ void k5_final(const float* __restrict__ Wf,
                         const float* __restrict__ bf,
                         float* __restrict__ res) {
    int gw   = (blockIdx.x * blockDim.x + threadIdx.x) >> 5;
    int lane = threadIdx.x & 31;
    if (gw >= HDIM * BATCH) return;
    int b = gw & 15, i = gw >> 4;
    const float4* wr = (const float4*)(Wf + (size_t)i * HDIM);
    const float4* orow = (const float4*)(g_o1 + b * HDIM);
    float acc = 0.f;
#pragma unroll
    for (int t = 0; t < 8; t++) {
        float4 w = wr[t * 32 + lane];
        float4 o = orow[t * 32 + lane];
        acc += w.x * o.x + w.y * o.y + w.z * o.z + w.w * o.w;
    }
#pragma unroll
    for (int o = 16; o > 0; o >>= 1) acc += __shfl_xor_sync(~0u, acc, o);
    if (lane == 0) res[b * HDIM + i] = acc + bf[i];
}

// ---------------------------------------------------------------------------
// launch
// ---------------------------------------------------------------------------
extern "C" void kernel_launch(void* const* d_in, const int* in_sizes, int n_in,
                              void* d_out, int out_size) {
    const float* query = (const float*)d_in[0];
    const float* key_  = (const float*)d_in[1];
    const float* value = (const float*)d_in[2];
    const float* Wq    = (const float*)d_in[3];
    const float* bq    = (const float*)d_in[4];
    const float* Wk    = (const float*)d_in[5];
    const float* bk    = (const float*)d_in[6];
    const float* Wv    = (const float*)d_in[7];
    const float* bv    = (const float*)d_in[8];
    const float* Wf    = (const float*)d_in[9];
    const float* bf    = (const float*)d_in[10];
    float* out = (float*)d_out;

    // kbuf 16384 + part 1024 + att_pk 512 + c 16 floats
    const int k3_smem = (16384 + 1024 + 512 + 16) * 4;   // 71744 B
    static bool attr_set = false;
    if (!attr_set) {
        cudaFuncSetAttribute(k3_fused, cudaFuncAttributeMaxDynamicSharedMemorySize, k3_smem);
        attr_set = true;
    }

    k1_q<<<(BATCH * HDIM * 32 + 255) / 256, 256>>>(query, Wq, bq);
    k2_w<<<HN * BATCH, 256>>>(Wk, bk);
    {
        dim3 grid(SEQ / 512, BATCH);   // 8 x 16 = 128 CTAs, single wave
        k3_fused<<<grid, 512, k3_smem>>>(key_, value);
    }
    k4_out<<<(HDIM * BATCH * 32 + 255) / 256, 256>>>(Wv, bv);
    k5_final<<<(HDIM * BATCH * 32 + 255) / 256, 256>>>(Wf, bf, out);
}